// round 4
// baseline (speedup 1.0000x reference)
#include <cuda_runtime.h>
#include <cuda_bf16.h>
#include <math.h>
#include <stdint.h>

// ---------------- problem constants ----------------
#define BATCH 4
#define SEQ   4096
#define HID_  1024
#define LC    1024
#define KSEL  512
#define WIN   256
#define NWIN  16
#define HC    4096

static const long N_TOK   = (long)BATCH * SEQ;
static const long SZ_FULL = N_TOK * HID_;
static const long SZ_COMP = (long)BATCH * LC * HID_;
static const long SZ_SC   = (long)BATCH * LC * LC;
static const long SZ_SEL  = (long)BATCH * KSEL * HID_;
static const long SZ_SS   = (long)BATCH * KSEL * KSEL;
static const long SZ_SW   = (long)BATCH * NWIN * WIN * WIN;

#define OFF_QF     0L
#define OFF_KF     (OFF_QF + SZ_FULL)
#define OFF_VF     (OFF_KF + SZ_FULL)
#define OFF_COMP   (OFF_VF + SZ_FULL)
#define OFF_QC     (OFF_COMP + SZ_COMP)
#define OFF_KC     (OFF_QC + SZ_COMP)
#define OFF_VC     (OFF_KC + SZ_COMP)
#define OFF_SC     (OFF_VC + SZ_COMP)
#define OFF_CPV    (OFF_SC + SZ_SC)
#define OFF_SQ     (OFF_CPV + SZ_COMP)
#define OFF_SK     (OFF_SQ + SZ_SEL)
#define OFF_SV     (OFF_SK + SZ_SEL)
#define OFF_SS     (OFF_SV + SZ_SEL)
#define OFF_SPV    (OFF_SS + SZ_SS)
#define OFF_SW     (OFF_SPV + SZ_SEL)
#define OFF_WPV    (OFF_SW + SZ_SW)
#define OFF_O      (OFF_WPV + SZ_FULL)
#define OFF_GATES  (OFF_O + SZ_FULL)
#define OFF_SCORES (OFF_GATES + N_TOK*3)
#define SCRATCH_TOTAL (OFF_SCORES + N_TOK)

__device__ __align__(1024) float g_scratch[SCRATCH_TOTAL];
__device__ int g_idx[BATCH * KSEL];

// ================= HMMA GEMM (mma.sync bf16, 3-term hi/lo split) =================
// C[M,N] = alpha * A[M,K] * B^T or B  (+bias)(+C)(*gate[row*3+gc])
// layoutB: 0 -> B is (N,K) row-major ; 1 -> B is (K,N) row-major.
// Tile 128x128, K-chunk 32. Smem holds bf16 fragments in register-layout order.

struct TCP {
    const float *A, *B, *bias, *gate;
    float *C;
    int K, lda, ldb, ldc;
    float alpha;
    int layoutB, accumulate, zdiv, gcomp;
    long aso, asi, bso, bsi, cso, csi, gso, gsi;
};

__device__ __forceinline__ void mma16816(float* d, const uint32_t* a, const uint32_t* b) {
    asm volatile(
        "mma.sync.aligned.m16n8k16.row.col.f32.bf16.bf16.f32 "
        "{%0,%1,%2,%3}, {%4,%5,%6,%7}, {%8,%9}, {%0,%1,%2,%3};"
        : "+f"(d[0]), "+f"(d[1]), "+f"(d[2]), "+f"(d[3])
        : "r"(a[0]), "r"(a[1]), "r"(a[2]), "r"(a[3]), "r"(b[0]), "r"(b[1]));
}

// fragment-layout smem addressing (region-relative byte offsets)
__device__ __forceinline__ int fragA_addr(int row, int col) {   // row 0..127, col(k) 0..31
    int tile = ((row >> 4) << 1) + (col >> 4);
    int lane = ((row & 7) << 2) + ((col & 7) >> 1);
    int w = ((row & 15) >> 3) + (((col & 15) >> 3) << 1);
    return tile * 512 + lane * 16 + w * 4 + ((col & 1) << 1);
}
__device__ __forceinline__ int fragB_addr(int n, int k) {       // n 0..127, k 0..31
    int tile = ((n >> 3) << 1) + (k >> 4);
    int lane = ((n & 7) << 2) + ((k & 7) >> 1);
    int w = (k & 15) >> 3;
    return tile * 256 + lane * 8 + w * 4 + ((k & 1) << 1);
}

__device__ __forceinline__ void bf_split(float v, uint16_t& h, uint16_t& l) {
    __nv_bfloat16 hb = __float2bfloat16(v);
    float r = v - __bfloat162float(hb);
    __nv_bfloat16 lb = __float2bfloat16(r);
    h = __bfloat16_as_ushort(hb);
    l = __bfloat16_as_ushort(lb);
}

__global__ void __launch_bounds__(256, 2) tc_gemm_k(TCP p) {
    __shared__ __align__(128) char sm[32768];
    char* smAh = sm;            // 8KB: A hi fragments
    char* smAl = sm + 8192;     // 8KB: A lo
    char* smBh = sm + 16384;    // 8KB: B hi
    char* smBl = sm + 24576;    // 8KB: B lo

    const int tid = threadIdx.x;
    const int wid = tid >> 5, lane = tid & 31;
    const int wm = wid & 3, wn = wid >> 2;     // warp covers rows wm*32..+31, cols wn*64..+63

    const long zo = blockIdx.z / p.zdiv, zi = blockIdx.z - zo * (long)p.zdiv;
    const float* A = p.A + zo * p.aso + zi * p.asi + (long)blockIdx.y * 128 * p.lda;
    const float* B = p.B + zo * p.bso + zi * p.bsi;
    if (p.layoutB == 0) B += (long)blockIdx.x * 128 * p.ldb;   // (N,K): advance rows
    else                B += (long)blockIdx.x * 128;           // (K,N): advance cols

    float acc[2][8][4];
#pragma unroll
    for (int mt = 0; mt < 2; mt++)
#pragma unroll
        for (int nt = 0; nt < 8; nt++)
#pragma unroll
            for (int r = 0; r < 4; r++) acc[mt][nt][r] = 0.f;

    const int nch = p.K >> 5;
    for (int c = 0; c < nch; c++) {
        const int k0 = c << 5;
        // ---- stage A (128 x 32) ----
#pragma unroll
        for (int i = 0; i < 4; i++) {
            int fi = tid + i * 256;
            int row = fi >> 3, kq = (fi & 7) << 2;
            float4 v = *(const float4*)(A + (long)row * p.lda + k0 + kq);
            uint16_t h0, l0, h1, l1, h2, l2, h3, l3;
            bf_split(v.x, h0, l0); bf_split(v.y, h1, l1);
            bf_split(v.z, h2, l2); bf_split(v.w, h3, l3);
            int a01 = fragA_addr(row, kq), a23 = fragA_addr(row, kq + 2);
            *(uint32_t*)(smAh + a01) = (uint32_t)h0 | ((uint32_t)h1 << 16);
            *(uint32_t*)(smAh + a23) = (uint32_t)h2 | ((uint32_t)h3 << 16);
            *(uint32_t*)(smAl + a01) = (uint32_t)l0 | ((uint32_t)l1 << 16);
            *(uint32_t*)(smAl + a23) = (uint32_t)l2 | ((uint32_t)l3 << 16);
        }
        // ---- stage B (128n x 32k) ----
        if (p.layoutB == 0) {
#pragma unroll
            for (int i = 0; i < 4; i++) {
                int fi = tid + i * 256;
                int n = fi >> 3, kq = (fi & 7) << 2;
                float4 v = *(const float4*)(B + (long)n * p.ldb + k0 + kq);
                uint16_t h0, l0, h1, l1, h2, l2, h3, l3;
                bf_split(v.x, h0, l0); bf_split(v.y, h1, l1);
                bf_split(v.z, h2, l2); bf_split(v.w, h3, l3);
                int b01 = fragB_addr(n, kq), b23 = fragB_addr(n, kq + 2);
                *(uint32_t*)(smBh + b01) = (uint32_t)h0 | ((uint32_t)h1 << 16);
                *(uint32_t*)(smBh + b23) = (uint32_t)h2 | ((uint32_t)h3 << 16);
                *(uint32_t*)(smBl + b01) = (uint32_t)l0 | ((uint32_t)l1 << 16);
                *(uint32_t*)(smBl + b23) = (uint32_t)l2 | ((uint32_t)l3 << 16);
            }
        } else {
#pragma unroll
            for (int i = 0; i < 4; i++) {
                int fi = tid + i * 256;
                int kr = fi >> 5, nq = (fi & 31) << 2;
                float4 v = *(const float4*)(B + (long)(k0 + kr) * p.ldb + nq);
                float vv[4] = {v.x, v.y, v.z, v.w};
#pragma unroll
                for (int j = 0; j < 4; j++) {
                    uint16_t h, l;
                    bf_split(vv[j], h, l);
                    int ba = fragB_addr(nq + j, kr);
                    *(uint16_t*)(smBh + ba) = h;
                    *(uint16_t*)(smBl + ba) = l;
                }
            }
        }
        __syncthreads();
        // ---- compute ----
#pragma unroll
        for (int ks = 0; ks < 2; ks++) {
            uint32_t aH[2][4], aL[2][4];
#pragma unroll
            for (int mt = 0; mt < 2; mt++) {
                int base = (((wm * 2 + mt) * 2 + ks) * 512) + lane * 16;
                *(uint4*)aH[mt] = *(uint4*)(smAh + base);
                *(uint4*)aL[mt] = *(uint4*)(smAl + base);
            }
#pragma unroll
            for (int nt = 0; nt < 8; nt++) {
                int base = (((wn * 8 + nt) * 2 + ks) * 256) + lane * 8;
                uint32_t bH[2], bL[2];
                *(uint2*)bH = *(uint2*)(smBh + base);
                *(uint2*)bL = *(uint2*)(smBl + base);
#pragma unroll
                for (int mt = 0; mt < 2; mt++) {
                    mma16816(acc[mt][nt], aH[mt], bH);
                    mma16816(acc[mt][nt], aH[mt], bL);
                    mma16816(acc[mt][nt], aL[mt], bH);
                }
            }
        }
        __syncthreads();
    }

    // ---- epilogue ----
    const float* gb = p.gate ? (p.gate + zo * p.gso + zi * p.gsi) : nullptr;
    float* C = p.C + zo * p.cso + zi * p.csi;
    const long rowBase = (long)blockIdx.y * 128 + wm * 32;
    const long colBase = (long)blockIdx.x * 128 + wn * 64;
    const int g = lane >> 2, t = lane & 3;
#pragma unroll
    for (int mt = 0; mt < 2; mt++) {
        long r0 = rowBase + mt * 16 + g;
        long r1 = r0 + 8;
        float gv0 = gb ? gb[r0 * 3 + p.gcomp] : 1.f;
        float gv1 = gb ? gb[r1 * 3 + p.gcomp] : 1.f;
#pragma unroll
        for (int nt = 0; nt < 8; nt++) {
            long col = colBase + nt * 8 + t * 2;
            float b0 = p.bias ? p.bias[col] : 0.f;
            float b1 = p.bias ? p.bias[col + 1] : 0.f;
            float* d = acc[mt][nt];
            long o0 = r0 * (long)p.ldc + col;
            long o1 = r1 * (long)p.ldc + col;
            float v0 = p.alpha * d[0] + b0, v1 = p.alpha * d[1] + b1;
            float v2 = p.alpha * d[2] + b0, v3 = p.alpha * d[3] + b1;
            if (p.accumulate) { v0 += C[o0]; v1 += C[o0 + 1]; v2 += C[o1]; v3 += C[o1 + 1]; }
            v0 *= gv0; v1 *= gv0; v2 *= gv1; v3 *= gv1;
            *(float2*)(C + o0) = make_float2(v0, v1);
            *(float2*)(C + o1) = make_float2(v2, v3);
        }
    }
}

static void run_tc(const float* A, const float* B, const float* bias, const float* gate,
                   float* C, int M, int N, int K, int lda, int ldb, int ldc,
                   float alpha, int layoutB, int accum, int nz, int zdiv,
                   long aso, long asi, long bso, long bsi, long cso, long csi,
                   long gso, long gsi, int gcomp) {
    TCP p;
    p.A = A; p.B = B; p.bias = bias; p.gate = gate; p.C = C;
    p.K = K; p.lda = lda; p.ldb = ldb; p.ldc = ldc;
    p.alpha = alpha; p.layoutB = layoutB; p.accumulate = accum;
    p.zdiv = zdiv; p.gcomp = gcomp;
    p.aso = aso; p.asi = asi; p.bso = bso; p.bsi = bsi;
    p.cso = cso; p.csi = csi; p.gso = gso; p.gsi = gsi;
    dim3 grid(N / 128, M / 128, nz);
    tc_gemm_k<<<grid, 256>>>(p);
}

// ================= gates + scores =================
__global__ void gates_scores_k(const float* __restrict__ x,
                               const float* __restrict__ Wg, const float* __restrict__ bg,
                               const float* __restrict__ Ws, const float* __restrict__ bs,
                               float* __restrict__ gates, float* __restrict__ scores) {
    int warp = threadIdx.x >> 5, lane = threadIdx.x & 31;
    long t = (long)blockIdx.x * 4 + warp;
    if (t >= N_TOK) return;
    const float* xr = x + t * HID_;
    float a0 = 0.f, a1 = 0.f, a2 = 0.f, a3 = 0.f;
    for (int d = lane; d < HID_; d += 32) {
        float xv = xr[d];
        a0 += xv * Wg[d * 3 + 0];
        a1 += xv * Wg[d * 3 + 1];
        a2 += xv * Wg[d * 3 + 2];
        a3 += xv * Ws[d];
    }
#pragma unroll
    for (int o = 16; o > 0; o >>= 1) {
        a0 += __shfl_down_sync(0xffffffffu, a0, o);
        a1 += __shfl_down_sync(0xffffffffu, a1, o);
        a2 += __shfl_down_sync(0xffffffffu, a2, o);
        a3 += __shfl_down_sync(0xffffffffu, a3, o);
    }
    if (lane == 0) {
        float g0 = 1.f / (1.f + expf(-(a0 + bg[0])));
        float g1 = 1.f / (1.f + expf(-(a1 + bg[1])));
        float g2 = 1.f / (1.f + expf(-(a2 + bg[2])));
        float s = g0 + g1 + g2 + 1e-6f;
        gates[t * 3 + 0] = g0 / s;
        gates[t * 3 + 1] = g1 / s;
        gates[t * 3 + 2] = g2 / s;
        scores[t] = a3 + bs[0];
    }
}

// ================= exact top-k =================
__device__ __forceinline__ bool before_f(float sa, int ia, float sb, int ib) {
    return (sa > sb) || (sa == sb && ia < ib);
}
__global__ void __launch_bounds__(512) topk_k(const float* __restrict__ scores, int* __restrict__ idx_out) {
    __shared__ float s[SEQ];
    __shared__ int id[SEQ];
    __shared__ int sel[KSEL];
    int b = blockIdx.x, tid = threadIdx.x;
    for (int i = tid; i < SEQ; i += 512) { s[i] = scores[(long)b * SEQ + i]; id[i] = i; }
    __syncthreads();
    for (int k = 2; k <= SEQ; k <<= 1)
        for (int j = k >> 1; j > 0; j >>= 1) {
            for (int i = tid; i < SEQ; i += 512) {
                int ixj = i ^ j;
                if (ixj > i) {
                    bool up = ((i & k) == 0);
                    bool ib = before_f(s[i], id[i], s[ixj], id[ixj]);
                    if (up ? !ib : ib) {
                        float ts = s[i]; s[i] = s[ixj]; s[ixj] = ts;
                        int ti = id[i]; id[i] = id[ixj]; id[ixj] = ti;
                    }
                }
            }
            __syncthreads();
        }
    if (tid < KSEL) sel[tid] = id[tid];
    __syncthreads();
    for (int k = 2; k <= KSEL; k <<= 1)
        for (int j = k >> 1; j > 0; j >>= 1) {
            int i = tid;
            if (i < KSEL) {
                int ixj = i ^ j;
                if (ixj > i) {
                    bool up = ((i & k) == 0);
                    if (up ? (sel[i] > sel[ixj]) : (sel[i] < sel[ixj])) {
                        int t = sel[i]; sel[i] = sel[ixj]; sel[ixj] = t;
                    }
                }
            }
            __syncthreads();
        }
    if (tid < KSEL) idx_out[b * KSEL + tid] = sel[tid];
}

// ================= gather =================
__global__ void gather_k(const float* __restrict__ Q, const float* __restrict__ K,
                         const float* __restrict__ V, const int* __restrict__ idx,
                         float* __restrict__ sq, float* __restrict__ sk, float* __restrict__ sv) {
    int r = blockIdx.x;
    int b = r >> 9;
    int src = idx[r];
    long so = ((long)b * SEQ + src) * HID_;
    long dofs = (long)r * HID_;
    for (int d = threadIdx.x; d < HID_; d += blockDim.x) {
        sq[dofs + d] = Q[so + d];
        sk[dofs + d] = K[so + d];
        sv[dofs + d] = V[so + d];
    }
}

// ================= softmax =================
__global__ void softmax_k(float* __restrict__ S, int N) {
    long base = (long)blockIdx.x * N;
    int tid = threadIdx.x;
    __shared__ float red[256];
    float m = -1e30f;
    for (int i = tid; i < N; i += 256) m = fmaxf(m, S[base + i]);
    red[tid] = m; __syncthreads();
    for (int o = 128; o > 0; o >>= 1) { if (tid < o) red[tid] = fmaxf(red[tid], red[tid + o]); __syncthreads(); }
    m = red[0]; __syncthreads();
    float sum = 0.f;
    for (int i = tid; i < N; i += 256) {
        float e = expf(S[base + i] - m);
        S[base + i] = e;
        sum += e;
    }
    red[tid] = sum; __syncthreads();
    for (int o = 128; o > 0; o >>= 1) { if (tid < o) red[tid] += red[tid + o]; __syncthreads(); }
    float inv = 1.f / red[0];
    for (int i = tid; i < N; i += 256) S[base + i] *= inv;
}

// ================= residual + layernorm =================
__global__ void final_ln_k(const float* __restrict__ O, const float* __restrict__ x,
                           float* __restrict__ out) {
    long base = (long)blockIdx.x * HID_;
    int tid = threadIdx.x;
    float y[4];
    float s = 0.f, ss = 0.f;
#pragma unroll
    for (int i = 0; i < 4; i++) {
        int c = tid + i * 256;
        float v = 0.5f * (O[base + c] + x[base + c]);
        y[i] = v; s += v; ss += v * v;
    }
    __shared__ float rs[32], rss[32];
    int lane = tid & 31, warp = tid >> 5;
#pragma unroll
    for (int o = 16; o > 0; o >>= 1) {
        s += __shfl_down_sync(0xffffffffu, s, o);
        ss += __shfl_down_sync(0xffffffffu, ss, o);
    }
    if (lane == 0) { rs[warp] = s; rss[warp] = ss; }
    __syncthreads();
    if (warp == 0) {
        s = (lane < 8) ? rs[lane] : 0.f;
        ss = (lane < 8) ? rss[lane] : 0.f;
#pragma unroll
        for (int o = 4; o > 0; o >>= 1) {
            s += __shfl_down_sync(0xffffffffu, s, o);
            ss += __shfl_down_sync(0xffffffffu, ss, o);
        }
        if (lane == 0) { rs[0] = s; rss[0] = ss; }
    }
    __syncthreads();
    float mu = rs[0] * (1.f / HID_);
    float var = rss[0] * (1.f / HID_) - mu * mu;
    float inv = rsqrtf(var + 1e-6f);
#pragma unroll
    for (int i = 0; i < 4; i++) {
        int c = tid + i * 256;
        out[base + c] = (y[i] - mu) * inv;
    }
}

// ================= launch =================
extern "C" void kernel_launch(void* const* d_in, const int* in_sizes, int n_in,
                              void* d_out, int out_size) {
    const float* x  = (const float*)d_in[0];
    const float* Wq = (const float*)d_in[1];
    const float* bq = (const float*)d_in[2];
    const float* Wk = (const float*)d_in[3];
    const float* bk = (const float*)d_in[4];
    const float* Wv = (const float*)d_in[5];
    const float* bv = (const float*)d_in[6];
    const float* Wo = (const float*)d_in[7];
    const float* bo = (const float*)d_in[8];
    const float* Wg = (const float*)d_in[9];
    const float* bg = (const float*)d_in[10];
    const float* Wc = (const float*)d_in[11];
    const float* bc = (const float*)d_in[12];
    const float* Ws = (const float*)d_in[13];
    const float* bs = (const float*)d_in[14];

    float* S; cudaGetSymbolAddress((void**)&S, g_scratch);
    int* idxp; cudaGetSymbolAddress((void**)&idxp, g_idx);

    float* Qf = S + OFF_QF;   float* Kf = S + OFF_KF;   float* Vf = S + OFF_VF;
    float* comp = S + OFF_COMP;
    float* Qc = S + OFF_QC;   float* Kc = S + OFF_KC;   float* Vc = S + OFF_VC;
    float* Sc = S + OFF_SC;   float* cPV = S + OFF_CPV;
    float* sQ = S + OFF_SQ;   float* sK = S + OFF_SK;   float* sV = S + OFF_SV;
    float* Ss = S + OFF_SS;   float* sPV = S + OFF_SPV;
    float* Sw = S + OFF_SW;   float* wPV = S + OFF_WPV;
    float* O  = S + OFF_O;
    float* gates = S + OFF_GATES;
    float* scores = S + OFF_SCORES;
    float* outp = (float*)d_out;

    const float SCALE = 0.125f;
    const int NN = 1, NT = 0;

    // gates + selection scores + top-k
    gates_scores_k<<<(int)(N_TOK / 4), 128>>>(x, Wg, bg, Ws, bs, gates, scores);
    topk_k<<<BATCH, 512>>>(scores, idxp);

    // full Q/K/V projections  (weights consumed natively as (K,N))
    run_tc(x, Wq, bq, nullptr, Qf, (int)N_TOK, HID_, HID_, HID_, HID_, HID_, 1.f, NN, 0, 1, 1, 0,0,0,0,0,0, 0,0,0);
    run_tc(x, Wk, bk, nullptr, Kf, (int)N_TOK, HID_, HID_, HID_, HID_, HID_, 1.f, NN, 0, 1, 1, 0,0,0,0,0,0, 0,0,0);
    run_tc(x, Wv, bv, nullptr, Vf, (int)N_TOK, HID_, HID_, HID_, HID_, HID_, 1.f, NN, 0, 1, 1, 0,0,0,0,0,0, 0,0,0);

    // compressed tokens + their Q/K/V
    run_tc(x, Wc, bc, nullptr, comp, BATCH * LC, HID_, HC, HC, HID_, HID_, 1.f, NN, 0, 1, 1, 0,0,0,0,0,0, 0,0,0);
    run_tc(comp, Wq, bq, nullptr, Qc, BATCH * LC, HID_, HID_, HID_, HID_, HID_, 1.f, NN, 0, 1, 1, 0,0,0,0,0,0, 0,0,0);
    run_tc(comp, Wk, bk, nullptr, Kc, BATCH * LC, HID_, HID_, HID_, HID_, HID_, 1.f, NN, 0, 1, 1, 0,0,0,0,0,0, 0,0,0);
    run_tc(comp, Wv, bv, nullptr, Vc, BATCH * LC, HID_, HID_, HID_, HID_, HID_, 1.f, NN, 0, 1, 1, 0,0,0,0,0,0, 0,0,0);

    // compressed attention (Kc consumed natively as (N,K))
    run_tc(Qc, Kc, nullptr, nullptr, Sc, LC, LC, HID_, HID_, HID_, LC, SCALE, NT, 0,
           BATCH, 1, (long)LC*HID_, 0, (long)LC*HID_, 0, (long)LC*LC, 0, 0, 0, 0);
    softmax_k<<<BATCH * LC, 256>>>(Sc, LC);
    run_tc(Sc, Vc, nullptr, gates, cPV, LC, HID_, LC, LC, HID_, HID_, 1.f, NN, 0,
           BATCH, 1, (long)LC*LC, 0, (long)LC*HID_, 0, (long)LC*HID_, 0, (long)SEQ*3, 0, 0);

    // selected branch
    gather_k<<<BATCH * KSEL, 256>>>(Qf, Kf, Vf, idxp, sQ, sK, sV);
    run_tc(sQ, sK, nullptr, nullptr, Ss, KSEL, KSEL, HID_, HID_, HID_, KSEL, SCALE, NT, 0,
           BATCH, 1, (long)KSEL*HID_, 0, (long)KSEL*HID_, 0, (long)KSEL*KSEL, 0, 0, 0, 0);
    softmax_k<<<BATCH * KSEL, 256>>>(Ss, KSEL);
    run_tc(Ss, sV, nullptr, gates, sPV, KSEL, HID_, KSEL, KSEL, HID_, HID_, 1.f, NN, 0,
           BATCH, 1, (long)KSEL*KSEL, 0, (long)KSEL*HID_, 0, (long)KSEL*HID_, 0, (long)SEQ*3, 0, 1);

    // window branch: 64 x (256x256) attentions on Q/K/V slices (stride 128 tokens)
    run_tc(Qf, Kf, nullptr, nullptr, Sw, WIN, WIN, HID_, HID_, HID_, WIN, SCALE, NT, 0,
           BATCH * NWIN, NWIN,
           (long)SEQ*HID_, (long)128*HID_,
           (long)SEQ*HID_, (long)128*HID_,
           (long)NWIN*WIN*WIN, (long)WIN*WIN, 0, 0, 0);
    softmax_k<<<BATCH * NWIN * WIN, 256>>>(Sw, WIN);
    run_tc(Sw, Vf, nullptr, gates, wPV, WIN, HID_, WIN, WIN, HID_, HID_, 1.f, NN, 0,
           BATCH * NWIN, NWIN,
           (long)NWIN*WIN*WIN, (long)WIN*WIN,
           (long)SEQ*HID_, (long)128*HID_,
           (long)NWIN*WIN*HID_, (long)WIN*HID_,
           (long)SEQ*3, (long)WIN*3, 2);

    // output projection (Wo row-blocks consumed natively as (K,N))
    run_tc(wPV, Wo + (long)2048 * HID_, bo, nullptr, O, (int)N_TOK, HID_, HID_, HID_, HID_, HID_,
           1.f, NN, 0, 1, 1, 0,0,0,0,0,0, 0,0,0);
    run_tc(cPV, Wo, nullptr, nullptr, O, LC, HID_, HID_, HID_, HID_, HID_, 1.f, NN, 1,
           BATCH, 1, (long)LC*HID_, 0, 0, 0, (long)SEQ*HID_, 0, 0, 0, 0);
    run_tc(sPV, Wo + (long)1024 * HID_, nullptr, nullptr, O, KSEL, HID_, HID_, HID_, HID_, HID_, 1.f, NN, 1,
           BATCH, 1, (long)KSEL*HID_, 0, 0, 0, (long)SEQ*HID_, 0, 0, 0, 0);

    // residual + layernorm
    final_ln_k<<<(int)N_TOK, 256>>>(O, x, outp);
}

// round 5
// speedup vs baseline: 4.1113x; 4.1113x over previous
#include <cuda_runtime.h>
#include <cuda_bf16.h>
#include <math.h>
#include <stdint.h>

// ---------------- problem constants ----------------
#define BATCH 4
#define SEQ   4096
#define HID_  1024
#define LC    1024
#define KSEL  512
#define WIN   256
#define NWIN  16

static const long N_TOK = (long)BATCH * SEQ;

// ---------------- scratch layout (bytes) ----------------
// bf16 split matrices store rows of length 2*K: per 32-orig-col block b,
// cols 64b..64b+31 = hi, 64b+32..64b+63 = lo.
constexpr long O_XB    = 0;                         // x split      (16384,2048)b
constexpr long O_QFB   = O_XB    + 67108864L;       // Qf split     (16384,2048)b
constexpr long O_KFB   = O_QFB   + 67108864L;       // Kf split
constexpr long O_VF    = O_KFB   + 67108864L;       // Vf fp32      (16384,1024)f
constexpr long O_TVFB  = O_VF    + 67108864L;       // Vf^T split   4x(1024,8192)b
constexpr long O_COMPB = O_TVFB  + 67108864L;       // comp split   (4096,2048)b
constexpr long O_QCB   = O_COMPB + 16777216L;
constexpr long O_KCB   = O_QCB   + 16777216L;
constexpr long O_VC    = O_KCB   + 16777216L;       // Vc fp32 (4096,1024)f
constexpr long O_TVCB  = O_VC    + 16777216L;       // Vc^T split 4x(1024,2048)b
constexpr long O_SC    = O_TVCB  + 16777216L;       // comp scores fp32 4x(1024,1024)f
constexpr long O_SCB   = O_SC    + 16777216L;       // comp P split 4x(1024,2048)b
constexpr long O_CPVB  = O_SCB   + 16777216L;       // comp PV split (4096,2048)b
constexpr long O_SQB   = O_CPVB  + 16777216L;       // sel Q split (2048,2048)b
constexpr long O_SKB   = O_SQB   + 8388608L;
constexpr long O_SV    = O_SKB   + 8388608L;        // sel V fp32 (2048,1024)f
constexpr long O_TSVB  = O_SV    + 8388608L;        // sel V^T split 4x(1024,1024)b
constexpr long O_SS    = O_TSVB  + 8388608L;        // sel scores fp32 4x(512,512)f
constexpr long O_SSB   = O_SS    + 4194304L;        // sel P split 4x(512,1024)b
constexpr long O_SPVB  = O_SSB   + 4194304L;        // sel PV split (2048,2048)b
constexpr long O_SW    = O_SPVB  + 8388608L;        // win scores fp32 64x(256,256)f
constexpr long O_SWB   = O_SW    + 16777216L;       // win P split 64x(256,512)b
constexpr long O_WPVB  = O_SWB   + 16777216L;       // win PV split (16384,2048)b
constexpr long O_O     = O_WPVB  + 67108864L;       // O fp32 (16384,1024)f
constexpr long O_TWQ   = O_O     + 67108864L;       // Wq^T split (1024,2048)b
constexpr long O_TWK   = O_TWQ   + 4194304L;
constexpr long O_TWV   = O_TWK   + 4194304L;
constexpr long O_TWC   = O_TWV   + 4194304L;        // Wc^T split (1024,8192)b
constexpr long O_TWO0  = O_TWC   + 16777216L;       // Wo blocks^T split (1024,2048)b
constexpr long O_TWO1  = O_TWO0  + 4194304L;
constexpr long O_TWO2  = O_TWO1  + 4194304L;
constexpr long O_GATES = O_TWO2  + 4194304L;        // (16384,3)f
constexpr long O_SCOR  = O_GATES + 196608L;         // (16384)f
constexpr long TOTALB  = O_SCOR  + 65536L;

__device__ __align__(1024) unsigned char g_scratch[TOTALB];
__device__ int g_idx[BATCH * KSEL];

typedef __nv_bfloat16 bf16;

// ================= PTX helpers =================
__device__ __forceinline__ uint32_t smem_u32(const void* p) {
    uint32_t a;
    asm("{ .reg .u64 t; cvta.to.shared.u64 t, %1; cvt.u32.u64 %0, t; }" : "=r"(a) : "l"(p));
    return a;
}
__device__ __forceinline__ void cp16(uint32_t dst, const void* src) {
    asm volatile("cp.async.cg.shared.global [%0], [%1], 16;" :: "r"(dst), "l"(src));
}
#define CP_COMMIT() asm volatile("cp.async.commit_group;" ::: "memory")
#define CP_WAIT1()  asm volatile("cp.async.wait_group 1;" ::: "memory")

__device__ __forceinline__ void ldm4(uint32_t* r, uint32_t addr) {
    asm volatile("ldmatrix.sync.aligned.m8n8.x4.shared.b16 {%0,%1,%2,%3}, [%4];"
        : "=r"(r[0]), "=r"(r[1]), "=r"(r[2]), "=r"(r[3]) : "r"(addr));
}
__device__ __forceinline__ void mma16816(float* d, const uint32_t* a, const uint32_t* b) {
    asm volatile(
        "mma.sync.aligned.m16n8k16.row.col.f32.bf16.bf16.f32 "
        "{%0,%1,%2,%3}, {%4,%5,%6,%7}, {%8,%9}, {%0,%1,%2,%3};"
        : "+f"(d[0]), "+f"(d[1]), "+f"(d[2]), "+f"(d[3])
        : "r"(a[0]), "r"(a[1]), "r"(a[2]), "r"(a[3]), "r"(b[0]), "r"(b[1]));
}
__device__ __forceinline__ void bf_split(float v, bf16& h, bf16& l) {
    h = __float2bfloat16(v);
    l = __float2bfloat16(v - __bfloat162float(h));
}

// ================= pipelined HMMA GEMM =================
// C[M,N] = alpha*A·B^T (+bias)(accum into Cf)(*gate(row)); A (M,2K), B (N,2K)
// bf16 split format. Tile 128x128, chunk 64 k2-cols, 3-stage cp.async pipeline.
struct GP {
    const bf16 *A, *B;
    const float *bias, *gate;
    float *Cf; bf16 *Cb;
    int K2, lda, ldb, ldcf, ldcb;
    float alpha;
    int accumulate, zdiv, gcomp;
    long aso, asi, bso, bsi, cfso, cfsi, cbso, cbsi, gso, gsi;
};

__device__ __forceinline__ void stage_load(uint32_t smb, int s, const bf16* A, const bf16* B,
                                           int lda, int ldb, int k2off, int tid) {
    uint32_t sa = smb + s * 32768;
    uint32_t sb2 = sa + 16384;
#pragma unroll
    for (int i = 0; i < 4; i++) {
        int idx = tid + i * 256;
        int row = idx >> 3, seg = idx & 7;
        cp16(sa + row * 128 + ((seg ^ (row & 7)) << 4), A + (long)row * lda + k2off + seg * 8);
    }
#pragma unroll
    for (int i = 0; i < 4; i++) {
        int idx = tid + i * 256;
        int row = idx >> 3, seg = idx & 7;
        cp16(sb2 + row * 128 + ((seg ^ (row & 7)) << 4), B + (long)row * ldb + k2off + seg * 8);
    }
    CP_COMMIT();
}

__device__ __forceinline__ uint32_t swz(uint32_t base, int r, int cb) {
    return base + r * 128 + ((((cb >> 4) ^ (r & 7))) << 4);
}

__global__ void __launch_bounds__(256, 2) gemm_k(GP p) {
    extern __shared__ __align__(1024) char sm[];
    uint32_t smb = smem_u32(sm);
    const int tid = threadIdx.x, lane = tid & 31, wid = tid >> 5;
    const int wm = wid & 3, wn = wid >> 2;

    const long zo = blockIdx.z / p.zdiv, zi = blockIdx.z - zo * (long)p.zdiv;
    const bf16* A = p.A + zo * p.aso + zi * p.asi + (long)blockIdx.y * 128 * p.lda;
    const bf16* B = p.B + zo * p.bso + zi * p.bsi + (long)blockIdx.x * 128 * p.ldb;

    float acc[2][8][4];
#pragma unroll
    for (int mt = 0; mt < 2; mt++)
#pragma unroll
        for (int nt = 0; nt < 8; nt++)
#pragma unroll
            for (int r = 0; r < 4; r++) acc[mt][nt][r] = 0.f;

    const int nch = p.K2 >> 6;
    stage_load(smb, 0, A, B, p.lda, p.ldb, 0, tid);
    stage_load(smb, 1, A, B, p.lda, p.ldb, 64, tid);

    for (int c = 0; c < nch; c++) {
        CP_WAIT1();
        __syncthreads();
        if (c + 2 < nch) stage_load(smb, (c + 2) % 3, A, B, p.lda, p.ldb, (c + 2) * 64, tid);
        else CP_COMMIT();

        uint32_t sa = smb + (c % 3) * 32768, sb2 = sa + 16384;
#pragma unroll
        for (int ks = 0; ks < 2; ks++) {
            uint32_t aH[2][4], aL[2][4];
            int ar = wm * 32 + (lane & 15);
            int acb = ks * 32 + ((lane >> 4) << 4);
#pragma unroll
            for (int mt = 0; mt < 2; mt++) {
                ldm4(aH[mt], swz(sa, ar + mt * 16, acb));
                ldm4(aL[mt], swz(sa, ar + mt * 16, acb + 64));
            }
            int br = wn * 64 + (lane & 7) + ((lane >> 4) << 3);
            int bcb = ks * 32 + (((lane >> 3) & 1) << 4);
#pragma unroll
            for (int nb = 0; nb < 4; nb++) {
                uint32_t h4[4], l4[4];
                ldm4(h4, swz(sb2, br + nb * 16, bcb));
                ldm4(l4, swz(sb2, br + nb * 16, bcb + 64));
#pragma unroll
                for (int sub = 0; sub < 2; sub++) {
                    int nt = nb * 2 + sub;
#pragma unroll
                    for (int mt = 0; mt < 2; mt++) {
                        mma16816(acc[mt][nt], aH[mt], h4 + sub * 2);
                        mma16816(acc[mt][nt], aH[mt], l4 + sub * 2);
                        mma16816(acc[mt][nt], aL[mt], h4 + sub * 2);
                    }
                }
            }
        }
        __syncthreads();
    }

    // ---- epilogue ----
    const float* gb = p.gate ? (p.gate + zo * p.gso + zi * p.gsi) : nullptr;
    float* Cf = p.Cf ? (p.Cf + zo * p.cfso + zi * p.cfsi) : nullptr;
    bf16* Cb = p.Cb ? (p.Cb + zo * p.cbso + zi * p.cbsi) : nullptr;
    const long rowBase = (long)blockIdx.y * 128 + wm * 32;
    const long colBase = (long)blockIdx.x * 128 + wn * 64;
    const int g = lane >> 2, t = lane & 3;
#pragma unroll
    for (int mt = 0; mt < 2; mt++) {
        long r0 = rowBase + mt * 16 + g, r1 = r0 + 8;
        float gv0 = gb ? gb[r0 * 3 + p.gcomp] : 1.f;
        float gv1 = gb ? gb[r1 * 3 + p.gcomp] : 1.f;
#pragma unroll
        for (int nt = 0; nt < 8; nt++) {
            long c = colBase + nt * 8 + t * 2;
            float b0 = p.bias ? p.bias[c] : 0.f;
            float b1 = p.bias ? p.bias[c + 1] : 0.f;
            float* d = acc[mt][nt];
            float v0 = p.alpha * d[0] + b0, v1 = p.alpha * d[1] + b1;
            float v2 = p.alpha * d[2] + b0, v3 = p.alpha * d[3] + b1;
            if (Cf) {
                long o0 = r0 * (long)p.ldcf + c, o1 = r1 * (long)p.ldcf + c;
                if (p.accumulate) { v0 += Cf[o0]; v1 += Cf[o0 + 1]; v2 += Cf[o1]; v3 += Cf[o1 + 1]; }
                v0 *= gv0; v1 *= gv0; v2 *= gv1; v3 *= gv1;
                *(float2*)(Cf + o0) = make_float2(v0, v1);
                *(float2*)(Cf + o1) = make_float2(v2, v3);
            } else {
                v0 *= gv0; v1 *= gv0; v2 *= gv1; v3 *= gv1;
            }
            if (Cb) {
                int oc = (int)(64 * (c >> 5) + (c & 31));
                bf16 h, l;
                __nv_bfloat162 hp, lp;
                bf_split(v0, h, l); hp.x = h; lp.x = l;
                bf_split(v1, h, l); hp.y = h; lp.y = l;
                *(__nv_bfloat162*)(Cb + r0 * (long)p.ldcb + oc) = hp;
                *(__nv_bfloat162*)(Cb + r0 * (long)p.ldcb + oc + 32) = lp;
                bf_split(v2, h, l); hp.x = h; lp.x = l;
                bf_split(v3, h, l); hp.y = h; lp.y = l;
                *(__nv_bfloat162*)(Cb + r1 * (long)p.ldcb + oc) = hp;
                *(__nv_bfloat162*)(Cb + r1 * (long)p.ldcb + oc + 32) = lp;
            }
        }
    }
}

static void run_gemm(const bf16* A, const bf16* B, const float* bias, const float* gate,
                     float* Cf, bf16* Cb, int M, int N, int K2,
                     int lda, int ldb, int ldcf, int ldcb, float alpha,
                     int accum, int nz, int zdiv,
                     long aso, long asi, long bso, long bsi,
                     long cfso, long cfsi, long cbso, long cbsi,
                     long gso, long gsi, int gcomp) {
    GP p;
    p.A = A; p.B = B; p.bias = bias; p.gate = gate; p.Cf = Cf; p.Cb = Cb;
    p.K2 = K2; p.lda = lda; p.ldb = ldb; p.ldcf = ldcf; p.ldcb = ldcb;
    p.alpha = alpha; p.accumulate = accum; p.zdiv = zdiv; p.gcomp = gcomp;
    p.aso = aso; p.asi = asi; p.bso = bso; p.bsi = bsi;
    p.cfso = cfso; p.cfsi = cfsi; p.cbso = cbso; p.cbsi = cbsi;
    p.gso = gso; p.gsi = gsi;
    dim3 grid(N / 128, M / 128, nz);
    gemm_k<<<grid, 256, 98304>>>(p);
}

// ================= straight convert: fp32 (R,C) -> bf16 split (R,2C) =================
__global__ void conv_k(const float* __restrict__ in, bf16* __restrict__ out, int C, long n4) {
    long i = (long)blockIdx.x * 256 + threadIdx.x;
    if (i >= n4) return;
    long e = i * 4;
    long row = e / C;
    int c = (int)(e - row * C);
    float4 v = *(const float4*)(in + e);
    long ob = row * (long)(2 * C) + 64 * (c >> 5) + (c & 31);
    bf16 h, l;
    bf_split(v.x, h, l); out[ob] = h;     out[ob + 32] = l;
    bf_split(v.y, h, l); out[ob + 1] = h; out[ob + 33] = l;
    bf_split(v.z, h, l); out[ob + 2] = h; out[ob + 34] = l;
    bf_split(v.w, h, l); out[ob + 3] = h; out[ob + 35] = l;
}

// ================= transpose convert: fp32 (R,C) -> bf16 split (C,2R), batched =================
__global__ void trconv_k(const float* __restrict__ in, bf16* __restrict__ out,
                         int R, int C, long ibs, long obs) {
    __shared__ float tbuf[32][33];
    in += (long)blockIdx.z * ibs;
    out += (long)blockIdx.z * obs;
    int r0 = blockIdx.y * 32, c0 = blockIdx.x * 32;
    int tx = threadIdx.x, ty = threadIdx.y;
#pragma unroll
    for (int i = 0; i < 4; i++)
        tbuf[ty + i * 8][tx] = in[(long)(r0 + ty + i * 8) * C + c0 + tx];
    __syncthreads();
    int ld2 = 2 * R;
#pragma unroll
    for (int i = 0; i < 4; i++) {
        int oc = ty + i * 8;
        float v = tbuf[tx][oc];
        bf16 h, l;
        bf_split(v, h, l);
        long ob = (long)(c0 + oc) * ld2 + 2 * r0;
        out[ob + tx] = h;
        out[ob + 32 + tx] = l;
    }
}

// ================= gates + scores =================
__global__ void gates_scores_k(const float* __restrict__ x,
                               const float* __restrict__ Wg, const float* __restrict__ bg,
                               const float* __restrict__ Ws, const float* __restrict__ bs,
                               float* __restrict__ gates, float* __restrict__ scores) {
    int warp = threadIdx.x >> 5, lane = threadIdx.x & 31;
    long t = (long)blockIdx.x * 4 + warp;
    if (t >= N_TOK) return;
    const float* xr = x + t * HID_;
    float a0 = 0.f, a1 = 0.f, a2 = 0.f, a3 = 0.f;
    for (int d = lane; d < HID_; d += 32) {
        float xv = xr[d];
        a0 += xv * Wg[d * 3 + 0];
        a1 += xv * Wg[d * 3 + 1];
        a2 += xv * Wg[d * 3 + 2];
        a3 += xv * Ws[d];
    }
#pragma unroll
    for (int o = 16; o > 0; o >>= 1) {
        a0 += __shfl_down_sync(0xffffffffu, a0, o);
        a1 += __shfl_down_sync(0xffffffffu, a1, o);
        a2 += __shfl_down_sync(0xffffffffu, a2, o);
        a3 += __shfl_down_sync(0xffffffffu, a3, o);
    }
    if (lane == 0) {
        float g0 = 1.f / (1.f + expf(-(a0 + bg[0])));
        float g1 = 1.f / (1.f + expf(-(a1 + bg[1])));
        float g2 = 1.f / (1.f + expf(-(a2 + bg[2])));
        float s = g0 + g1 + g2 + 1e-6f;
        gates[t * 3 + 0] = g0 / s;
        gates[t * 3 + 1] = g1 / s;
        gates[t * 3 + 2] = g2 / s;
        scores[t] = a3 + bs[0];
    }
}

// ================= exact top-k =================
__device__ __forceinline__ bool before_f(float sa, int ia, float sb, int ib) {
    return (sa > sb) || (sa == sb && ia < ib);
}
__global__ void __launch_bounds__(512) topk_k(const float* __restrict__ scores, int* __restrict__ idx_out) {
    __shared__ float s[SEQ];
    __shared__ int id[SEQ];
    __shared__ int sel[KSEL];
    int b = blockIdx.x, tid = threadIdx.x;
    for (int i = tid; i < SEQ; i += 512) { s[i] = scores[(long)b * SEQ + i]; id[i] = i; }
    __syncthreads();
    for (int k = 2; k <= SEQ; k <<= 1)
        for (int j = k >> 1; j > 0; j >>= 1) {
            for (int i = tid; i < SEQ; i += 512) {
                int ixj = i ^ j;
                if (ixj > i) {
                    bool up = ((i & k) == 0);
                    bool ib = before_f(s[i], id[i], s[ixj], id[ixj]);
                    if (up ? !ib : ib) {
                        float ts = s[i]; s[i] = s[ixj]; s[ixj] = ts;
                        int ti = id[i]; id[i] = id[ixj]; id[ixj] = ti;
                    }
                }
            }
            __syncthreads();
        }
    if (tid < KSEL) sel[tid] = id[tid];
    __syncthreads();
    for (int k = 2; k <= KSEL; k <<= 1)
        for (int j = k >> 1; j > 0; j >>= 1) {
            int i = tid;
            if (i < KSEL) {
                int ixj = i ^ j;
                if (ixj > i) {
                    bool up = ((i & k) == 0);
                    if (up ? (sel[i] > sel[ixj]) : (sel[i] < sel[ixj])) {
                        int tt = sel[i]; sel[i] = sel[ixj]; sel[ixj] = tt;
                    }
                }
            }
            __syncthreads();
        }
    if (tid < KSEL) idx_out[b * KSEL + tid] = sel[tid];
}

// ================= gather (bf16 Q/K rows, fp32 V rows) =================
__global__ void gather_k(const bf16* __restrict__ Qb, const bf16* __restrict__ Kb,
                         const float* __restrict__ V, const int* __restrict__ idx,
                         bf16* __restrict__ sq, bf16* __restrict__ sk, float* __restrict__ sv) {
    int r = blockIdx.x;
    int b = r >> 9;
    long srow = (long)b * SEQ + idx[r];
    int tid = threadIdx.x;
    const uint4* q4 = (const uint4*)(Qb + srow * 2048);
    const uint4* k4 = (const uint4*)(Kb + srow * 2048);
    const uint4* v4 = (const uint4*)(V + srow * 1024);
    uint4* oq = (uint4*)(sq + (long)r * 2048);
    uint4* ok = (uint4*)(sk + (long)r * 2048);
    uint4* ov = (uint4*)(sv + (long)r * 1024);
    oq[tid] = q4[tid];
    ok[tid] = k4[tid];
    ov[tid] = v4[tid];
}

// ================= softmax (fp32 in, bf16 split out) =================
__global__ void softmax_k(const float* __restrict__ S, bf16* __restrict__ Pb, int N) {
    __shared__ float buf[1024];
    __shared__ float red[256];
    long base = (long)blockIdx.x * N;
    long base2 = (long)blockIdx.x * 2 * N;
    int tid = threadIdx.x;
    float m = -1e30f;
    for (int i = tid; i < N; i += 256) { float xv = S[base + i]; buf[i] = xv; m = fmaxf(m, xv); }
    red[tid] = m; __syncthreads();
    for (int o = 128; o > 0; o >>= 1) { if (tid < o) red[tid] = fmaxf(red[tid], red[tid + o]); __syncthreads(); }
    m = red[0]; __syncthreads();
    float sum = 0.f;
    for (int i = tid; i < N; i += 256) { float e = expf(buf[i] - m); buf[i] = e; sum += e; }
    red[tid] = sum; __syncthreads();
    for (int o = 128; o > 0; o >>= 1) { if (tid < o) red[tid] += red[tid + o]; __syncthreads(); }
    float inv = 1.f / red[0];
    __syncthreads();
    for (int i = tid; i < N; i += 256) {
        float pv = buf[i] * inv;
        bf16 h, l;
        bf_split(pv, h, l);
        long ob = base2 + 64 * (i >> 5) + (i & 31);
        Pb[ob] = h;
        Pb[ob + 32] = l;
    }
}

// ================= residual + layernorm =================
__global__ void final_ln_k(const float* __restrict__ O, const float* __restrict__ x,
                           float* __restrict__ out) {
    long base = (long)blockIdx.x * HID_;
    int tid = threadIdx.x;
    float y[4];
    float s = 0.f, ss = 0.f;
#pragma unroll
    for (int i = 0; i < 4; i++) {
        int c = tid + i * 256;
        float v = 0.5f * (O[base + c] + x[base + c]);
        y[i] = v; s += v; ss += v * v;
    }
    __shared__ float rs[32], rss[32];
    int lane = tid & 31, warp = tid >> 5;
#pragma unroll
    for (int o = 16; o > 0; o >>= 1) {
        s += __shfl_down_sync(0xffffffffu, s, o);
        ss += __shfl_down_sync(0xffffffffu, ss, o);
    }
    if (lane == 0) { rs[warp] = s; rss[warp] = ss; }
    __syncthreads();
    if (warp == 0) {
        s = (lane < 8) ? rs[lane] : 0.f;
        ss = (lane < 8) ? rss[lane] : 0.f;
#pragma unroll
        for (int o = 4; o > 0; o >>= 1) {
            s += __shfl_down_sync(0xffffffffu, s, o);
            ss += __shfl_down_sync(0xffffffffu, ss, o);
        }
        if (lane == 0) { rs[0] = s; rss[0] = ss; }
    }
    __syncthreads();
    float mu = rs[0] * (1.f / HID_);
    float var = rss[0] * (1.f / HID_) - mu * mu;
    float inv = rsqrtf(var + 1e-6f);
#pragma unroll
    for (int i = 0; i < 4; i++) {
        int c = tid + i * 256;
        out[base + c] = (y[i] - mu) * inv;
    }
}

// ================= launch =================
extern "C" void kernel_launch(void* const* d_in, const int* in_sizes, int n_in,
                              void* d_out, int out_size) {
    const float* x  = (const float*)d_in[0];
    const float* Wq = (const float*)d_in[1];
    const float* bq = (const float*)d_in[2];
    const float* Wk = (const float*)d_in[3];
    const float* bk = (const float*)d_in[4];
    const float* Wv = (const float*)d_in[5];
    const float* bv = (const float*)d_in[6];
    const float* Wo = (const float*)d_in[7];
    const float* bo = (const float*)d_in[8];
    const float* Wg = (const float*)d_in[9];
    const float* bg = (const float*)d_in[10];
    const float* Wc = (const float*)d_in[11];
    const float* bc = (const float*)d_in[12];
    const float* Ws = (const float*)d_in[13];
    const float* bs = (const float*)d_in[14];

    cudaFuncSetAttribute(gemm_k, cudaFuncAttributeMaxDynamicSharedMemorySize, 98304);

    unsigned char* G; cudaGetSymbolAddress((void**)&G, g_scratch);
    int* idxp; cudaGetSymbolAddress((void**)&idxp, g_idx);

    bf16* xb    = (bf16*)(G + O_XB);
    bf16* Qfb   = (bf16*)(G + O_QFB);
    bf16* Kfb   = (bf16*)(G + O_KFB);
    float* Vf   = (float*)(G + O_VF);
    bf16* tVfb  = (bf16*)(G + O_TVFB);
    bf16* compb = (bf16*)(G + O_COMPB);
    bf16* Qcb   = (bf16*)(G + O_QCB);
    bf16* Kcb   = (bf16*)(G + O_KCB);
    float* Vc   = (float*)(G + O_VC);
    bf16* tVcb  = (bf16*)(G + O_TVCB);
    float* Sc   = (float*)(G + O_SC);
    bf16* Scb   = (bf16*)(G + O_SCB);
    bf16* cPVb  = (bf16*)(G + O_CPVB);
    bf16* sQb   = (bf16*)(G + O_SQB);
    bf16* sKb   = (bf16*)(G + O_SKB);
    float* sV   = (float*)(G + O_SV);
    bf16* tSvb  = (bf16*)(G + O_TSVB);
    float* Ss   = (float*)(G + O_SS);
    bf16* Ssb   = (bf16*)(G + O_SSB);
    bf16* sPVb  = (bf16*)(G + O_SPVB);
    float* Sw   = (float*)(G + O_SW);
    bf16* Swb   = (bf16*)(G + O_SWB);
    bf16* wPVb  = (bf16*)(G + O_WPVB);
    float* O    = (float*)(G + O_O);
    bf16* tWq   = (bf16*)(G + O_TWQ);
    bf16* tWk   = (bf16*)(G + O_TWK);
    bf16* tWv   = (bf16*)(G + O_TWV);
    bf16* tWc   = (bf16*)(G + O_TWC);
    bf16* tWo0  = (bf16*)(G + O_TWO0);
    bf16* tWo1  = (bf16*)(G + O_TWO1);
    bf16* tWo2  = (bf16*)(G + O_TWO2);
    float* gates  = (float*)(G + O_GATES);
    float* scores = (float*)(G + O_SCOR);
    float* outp = (float*)d_out;

    const float SCALE = 0.125f;
    dim3 trb(32, 8);

    // operand conversions
    conv_k<<<(int)((N_TOK * HID_ / 4 + 255) / 256), 256>>>(x, xb, HID_, N_TOK * HID_ / 4);
    trconv_k<<<dim3(32, 32, 1), trb>>>(Wq, tWq, 1024, 1024, 0, 0);
    trconv_k<<<dim3(32, 32, 1), trb>>>(Wk, tWk, 1024, 1024, 0, 0);
    trconv_k<<<dim3(32, 32, 1), trb>>>(Wv, tWv, 1024, 1024, 0, 0);
    trconv_k<<<dim3(32, 128, 1), trb>>>(Wc, tWc, 4096, 1024, 0, 0);
    trconv_k<<<dim3(32, 32, 1), trb>>>(Wo, tWo0, 1024, 1024, 0, 0);
    trconv_k<<<dim3(32, 32, 1), trb>>>(Wo + 1024L * 1024, tWo1, 1024, 1024, 0, 0);
    trconv_k<<<dim3(32, 32, 1), trb>>>(Wo + 2048L * 1024, tWo2, 1024, 1024, 0, 0);

    // gates + selection scores + top-k
    gates_scores_k<<<(int)(N_TOK / 4), 128>>>(x, Wg, bg, Ws, bs, gates, scores);
    topk_k<<<BATCH, 512>>>(scores, idxp);

    // full Q/K/V projections
    run_gemm(xb, tWq, bq, nullptr, nullptr, Qfb, (int)N_TOK, 1024, 2048, 2048, 2048, 0, 2048,
             1.f, 0, 1, 1, 0,0,0,0, 0,0, 0,0, 0,0, 0);
    run_gemm(xb, tWk, bk, nullptr, nullptr, Kfb, (int)N_TOK, 1024, 2048, 2048, 2048, 0, 2048,
             1.f, 0, 1, 1, 0,0,0,0, 0,0, 0,0, 0,0, 0);
    run_gemm(xb, tWv, bv, nullptr, Vf, nullptr, (int)N_TOK, 1024, 2048, 2048, 2048, 1024, 0,
             1.f, 0, 1, 1, 0,0,0,0, 0,0, 0,0, 0,0, 0);

    // compressed tokens (x viewed as (4096, 8192) split) + their Q/K/V
    run_gemm(xb, tWc, bc, nullptr, nullptr, compb, 4096, 1024, 8192, 8192, 8192, 0, 2048,
             1.f, 0, 1, 1, 0,0,0,0, 0,0, 0,0, 0,0, 0);
    run_gemm(compb, tWq, bq, nullptr, nullptr, Qcb, 4096, 1024, 2048, 2048, 2048, 0, 2048,
             1.f, 0, 1, 1, 0,0,0,0, 0,0, 0,0, 0,0, 0);
    run_gemm(compb, tWk, bk, nullptr, nullptr, Kcb, 4096, 1024, 2048, 2048, 2048, 0, 2048,
             1.f, 0, 1, 1, 0,0,0,0, 0,0, 0,0, 0,0, 0);
    run_gemm(compb, tWv, bv, nullptr, Vc, nullptr, 4096, 1024, 2048, 2048, 2048, 1024, 0,
             1.f, 0, 1, 1, 0,0,0,0, 0,0, 0,0, 0,0, 0);

    // compressed attention
    run_gemm(Qcb, Kcb, nullptr, nullptr, Sc, nullptr, 1024, 1024, 2048, 2048, 2048, 1024, 0,
             SCALE, 0, BATCH, 1, 1024L*2048, 0, 1024L*2048, 0, 1024L*1024, 0, 0,0, 0,0, 0);
    softmax_k<<<BATCH * 1024, 256>>>(Sc, Scb, 1024);
    trconv_k<<<dim3(32, 32, BATCH), trb>>>(Vc, tVcb, 1024, 1024, 1024L*1024, 1024L*2048);
    run_gemm(Scb, tVcb, nullptr, gates, nullptr, cPVb, 1024, 1024, 2048, 2048, 2048, 0, 2048,
             1.f, 0, BATCH, 1, 1024L*2048, 0, 1024L*2048, 0, 0,0, 1024L*2048, 0,
             (long)SEQ*3, 0, 0);

    // selected branch
    gather_k<<<BATCH * KSEL, 256>>>(Qfb, Kfb, Vf, idxp, sQb, sKb, sV);
    run_gemm(sQb, sKb, nullptr, nullptr, Ss, nullptr, 512, 512, 2048, 2048, 2048, 512, 0,
             SCALE, 0, BATCH, 1, 512L*2048, 0, 512L*2048, 0, 512L*512, 0, 0,0, 0,0, 0);
    softmax_k<<<BATCH * 512, 256>>>(Ss, Ssb, 512);
    trconv_k<<<dim3(32, 16, BATCH), trb>>>(sV, tSvb, 512, 1024, 512L*1024, 1024L*1024);
    run_gemm(Ssb, tSvb, nullptr, gates, nullptr, sPVb, 512, 1024, 1024, 1024, 1024, 0, 2048,
             1.f, 0, BATCH, 1, 512L*1024, 0, 1024L*1024, 0, 0,0, 512L*2048, 0,
             (long)SEQ*3, 0, 1);

    // window branch
    trconv_k<<<dim3(32, 128, BATCH), trb>>>(Vf, tVfb, 4096, 1024, 4096L*1024, 1024L*8192);
    run_gemm(Qfb, Kfb, nullptr, nullptr, Sw, nullptr, WIN, WIN, 2048, 2048, 2048, WIN, 0,
             SCALE, 0, BATCH * NWIN, NWIN,
             (long)SEQ*2048, 128L*2048, (long)SEQ*2048, 128L*2048,
             (long)NWIN*WIN*WIN, (long)WIN*WIN, 0,0, 0,0, 0);
    softmax_k<<<BATCH * NWIN * WIN, 256>>>(Sw, Swb, WIN);
    run_gemm(Swb, tVfb, nullptr, gates, nullptr, wPVb, WIN, 1024, 512, 512, 8192, 0, 2048,
             1.f, 0, BATCH * NWIN, NWIN,
             (long)NWIN*WIN*512, (long)WIN*512,
             1024L*8192, 256,
             0,0, (long)SEQ*2048, (long)WIN*2048,
             (long)SEQ*3, (long)WIN*3, 2);

    // output projection (Wo row-block split; comp/sel branches zero-padded)
    run_gemm(wPVb, tWo2, bo, nullptr, O, nullptr, (int)N_TOK, 1024, 2048, 2048, 2048, 1024, 0,
             1.f, 0, 1, 1, 0,0,0,0, 0,0, 0,0, 0,0, 0);
    run_gemm(cPVb, tWo0, nullptr, nullptr, O, nullptr, 1024, 1024, 2048, 2048, 2048, 1024, 0,
             1.f, 1, BATCH, 1, 1024L*2048, 0, 0, 0, (long)SEQ*1024, 0, 0,0, 0,0, 0);
    run_gemm(sPVb, tWo1, nullptr, nullptr, O, nullptr, 512, 1024, 2048, 2048, 2048, 1024, 0,
             1.f, 1, BATCH, 1, 512L*2048, 0, 0, 0, (long)SEQ*1024, 0, 0,0, 0,0, 0);

    // residual + layernorm
    final_ln_k<<<(int)N_TOK, 256>>>(O, x, outp);
}